// round 12
// baseline (speedup 1.0000x reference)
#include <cuda_runtime.h>
#include <cuda_fp16.h>
#include <cstdint>

// Problem constants (fixed by the dataset)
#define IN_F   4096
#define OUT_F  11008
#define GROUPS 32       // IN_F / 128
#define BM 128
#define BN 128
#define BK 64           // k-halves per stage (128 bytes per row)
#define STAGES 3
#define STAGE_A_BYTES (BM * 128)                       // 16384
#define STAGE_BYTES   (STAGE_A_BYTES + BN * 128)       // 32768
#define KT (IN_F / BK)  // 64

// Dequantized weights, fp16, [OUT_F][IN_F] row-major (K contiguous).
__device__ __half g_W[(size_t)OUT_F * IN_F];
// Activations converted to fp16, [M][IN_F].
__device__ __half g_X[(size_t)4096 * IN_F];

// ---------------------------------------------------------------------------
// Fused prep: blocks [0, nconv) convert x f32->fp16; the rest dequantize W.
// ---------------------------------------------------------------------------
__global__ void prep_kernel(const float4* __restrict__ xin, int n_x, int nconv,
                            const int4* __restrict__ qw,
                            const float* __restrict__ scales,
                            const int* __restrict__ qz) {
    if ((int)blockIdx.x < nconv) {
        int i = (blockIdx.x * blockDim.x + threadIdx.x) * 8;
        if (i >= n_x) return;
        float4 a = xin[i / 4];
        float4 b = xin[i / 4 + 1];
        __half2 h[4];
        h[0] = __floats2half2_rn(a.x, a.y);
        h[1] = __floats2half2_rn(a.z, a.w);
        h[2] = __floats2half2_rn(b.x, b.y);
        h[3] = __floats2half2_rn(b.z, b.w);
        *reinterpret_cast<uint4*>(g_X + i) = *reinterpret_cast<uint4*>(h);
    } else {
        const int JP = IN_F / 8;  // 512 int4-chunks per output row
        int idx = (blockIdx.x - nconv) * blockDim.x + threadIdx.x;
        if (idx >= OUT_F * JP) return;

        int o  = idx / JP;
        int jq = idx - o * JP;
        int g  = jq >> 4;           // group = (jq*8)/128

        int4 v = qw[idx];
        int zb = qz[o * (GROUPS / 2) + (g >> 1)];
        int z  = (g & 1) ? ((zb >> 4) & 15) : (zb & 15);
        float s = scales[o * GROUPS + g];

        int q[4] = {v.x, v.y, v.z, v.w};
        __half2 h[4];
#pragma unroll
        for (int t = 0; t < 4; t++) {
            float w0 = (float)((q[t] & 15) - z) * s;
            float w1 = (float)(((q[t] >> 4) & 15) - z) * s;
            h[t] = __floats2half2_rn(w0, w1);
        }
        *reinterpret_cast<uint4*>(g_W + (size_t)idx * 8) = *reinterpret_cast<uint4*>(h);
    }
}

// ---------------------------------------------------------------------------
// GEMM: C[M][OUT_F] (f32) = A[M][IN_F] (f16) * W^T
// TN mma.sync.m16n8k16. BM=BN=128 BK=64, 3-stage cp.async, SW128 smem,
// 4 warps (2x2), warp tile 64x64, 2 CTAs/SM. Cross-stage register fragment
// pipeline: next stage's ks0 fragments prefetched during ks3; single
// __syncthreads per kt placed after ks2's MMA issue (hidden under tensor).
// ---------------------------------------------------------------------------
__device__ __forceinline__ uint32_t sw128(uint32_t o) {
    return o ^ ((o >> 3) & 0x70);
}

__device__ __forceinline__ void cp_async16(uint32_t saddr, const void* gptr) {
    asm volatile("cp.async.cg.shared.global [%0], [%1], 16;\n"
                 :: "r"(saddr), "l"(gptr) : "memory");
}

// One quarter of a k-stage load: 2 A-chunks + 2 B-chunks per thread.
__device__ __forceinline__ void load_quarter(uint32_t sA,
                                             const __half* __restrict__ Ag,
                                             const __half* __restrict__ Bg,
                                             int m0, int n0, int k0, int tid,
                                             int q) {
    uint32_t sB = sA + STAGE_A_BYTES;
#pragma unroll
    for (int i = 2 * q; i < 2 * q + 2; i++) {
        int chunk = tid + i * 128;
        int r = chunk >> 3;
        int c = chunk & 7;
        cp_async16(sA + sw128((uint32_t)(r * 128 + c * 16)),
                   Ag + (size_t)(m0 + r) * IN_F + k0 + c * 8);
    }
#pragma unroll
    for (int i = 2 * q; i < 2 * q + 2; i++) {
        int chunk = tid + i * 128;
        int r = chunk >> 3;
        int c = chunk & 7;
        cp_async16(sB + sw128((uint32_t)(r * 128 + c * 16)),
                   Bg + (size_t)(n0 + r) * IN_F + k0 + c * 8);
    }
}

// Full stage load (prologue only).
__device__ __forceinline__ void load_tiles(uint32_t sA,
                                           const __half* __restrict__ Ag,
                                           const __half* __restrict__ Bg,
                                           int m0, int n0, int k0, int tid) {
#pragma unroll
    for (int q = 0; q < 4; q++)
        load_quarter(sA, Ag, Bg, m0, n0, k0, tid, q);
}

// Load one ks-step's register fragments (a: 4 x ldmatrix.x4, b: 4 x ldmatrix.x4)
__device__ __forceinline__ void load_frags(uint32_t sA, int ks,
                                           int wm, int wn, int lane,
                                           uint32_t a[4][4], uint32_t b[8][2]) {
    uint32_t sB = sA + STAGE_A_BYTES;
    const int cb = ks * 32 + ((lane >> 4) << 4);  // byte col within 128B row
#pragma unroll
    for (int mf = 0; mf < 4; mf++) {
        int r = wm * 64 + mf * 16 + (lane & 15);
        uint32_t addr = sA + sw128((uint32_t)(r * 128 + cb));
        asm volatile(
            "ldmatrix.sync.aligned.m8n8.x4.shared.b16 {%0,%1,%2,%3}, [%4];\n"
            : "=r"(a[mf][0]), "=r"(a[mf][1]), "=r"(a[mf][2]), "=r"(a[mf][3])
            : "r"(addr));
    }
#pragma unroll
    for (int p = 0; p < 4; p++) {
        int r = wn * 64 + p * 16 + (lane & 15);
        uint32_t addr = sB + sw128((uint32_t)(r * 128 + cb));
        uint32_t r0, r1, r2, r3;
        asm volatile(
            "ldmatrix.sync.aligned.m8n8.x4.shared.b16 {%0,%1,%2,%3}, [%4];\n"
            : "=r"(r0), "=r"(r1), "=r"(r2), "=r"(r3)
            : "r"(addr));
        // reg0: n[0..7] k[0..7], reg1: n[8..15] k[0..7],
        // reg2: n[0..7] k[8..15], reg3: n[8..15] k[8..15]
        b[p * 2 + 0][0] = r0; b[p * 2 + 0][1] = r2;
        b[p * 2 + 1][0] = r1; b[p * 2 + 1][1] = r3;
    }
}

__global__ void __launch_bounds__(128, 2)
gemm_kernel(float* __restrict__ C) {
    extern __shared__ char smem[];
    const __half* __restrict__ A = g_X;
    const __half* __restrict__ B = g_W;

    const int tid  = threadIdx.x;
    const int lane = tid & 31;
    const int warp = tid >> 5;
    const int wm   = warp & 1;     // 0..1 -> m offset wm*64
    const int wn   = warp >> 1;    // 0..1 -> n offset wn*64
    const int m0   = blockIdx.x * BM;
    const int n0   = blockIdx.y * BN;

    uint32_t sbase = (uint32_t)__cvta_generic_to_shared(smem);

    float acc[4][8][4];
#pragma unroll
    for (int i = 0; i < 4; i++)
#pragma unroll
        for (int j = 0; j < 8; j++)
#pragma unroll
            for (int k = 0; k < 4; k++) acc[i][j][k] = 0.0f;

    // Prologue: stages 0,1
    load_tiles(sbase + 0 * STAGE_BYTES, A, B, m0, n0, 0 * BK, tid);
    asm volatile("cp.async.commit_group;\n" ::: "memory");
    load_tiles(sbase + 1 * STAGE_BYTES, A, B, m0, n0, 1 * BK, tid);
    asm volatile("cp.async.commit_group;\n" ::: "memory");
    asm volatile("cp.async.wait_group 1;\n" ::: "memory");
    __syncthreads();

    uint32_t a[2][4][4];
    uint32_t b[2][8][2];

    // Pre-load kt=0/ks=0 fragments
    load_frags(sbase, 0, wm, wn, lane, a[0], b[0]);

    int slot = 0;
    for (int kt = 0; kt < KT; kt++) {
        int slotN = slot + 1; if (slotN == STAGES) slotN = 0;
        int slotL = slotN + 1; if (slotL == STAGES) slotL = 0;
        uint32_t sCur  = sbase + slot  * STAGE_BYTES;
        uint32_t sNext = sbase + slotN * STAGE_BYTES;
        uint32_t sLoad = sbase + slotL * STAGE_BYTES;
        const int  kn      = kt + 2;
        const bool do_load = (kn < KT);
        const int  kload   = kn * BK;

#pragma unroll
        for (int ks = 0; ks < 4; ks++) {
            int cur = ks & 1;
            // Prefetch next fragments (same stage for ks<3; next stage's ks0
            // at ks==3 — certified by the wait+bar at end of ks2).
            if (ks < 3)
                load_frags(sCur, ks + 1, wm, wn, lane, a[cur ^ 1], b[cur ^ 1]);
            else if (kt + 1 < KT)
                load_frags(sNext, 0, wm, wn, lane, a[cur ^ 1], b[cur ^ 1]);
            // Interleaved global prefetch quarter for stage kt+2.
            if (do_load)
                load_quarter(sLoad, A, B, m0, n0, kload, tid, ks);
            // MMA block for this ks.
#pragma unroll
            for (int mf = 0; mf < 4; mf++) {
#pragma unroll
                for (int nf = 0; nf < 8; nf++) {
                    float* c = acc[mf][nf];
                    asm volatile(
                        "mma.sync.aligned.m16n8k16.row.col.f32.f16.f16.f32 "
                        "{%0,%1,%2,%3}, {%4,%5,%6,%7}, {%8,%9}, {%0,%1,%2,%3};\n"
                        : "+f"(c[0]), "+f"(c[1]), "+f"(c[2]), "+f"(c[3])
                        : "r"(a[cur][mf][0]), "r"(a[cur][mf][1]),
                          "r"(a[cur][mf][2]), "r"(a[cur][mf][3]),
                          "r"(b[cur][nf][0]), "r"(b[cur][nf][1]));
                }
            }
            if (ks == 2) {
                // All reads of stage kt are issued (ks3 frags prefetched above)
                // and stage kt+1's group is the only committed outstanding one.
                // Barrier latency hides under the ks2 MMA block just issued.
                asm volatile("cp.async.wait_group 0;\n" ::: "memory");
                __syncthreads();
            }
        }
        asm volatile("cp.async.commit_group;\n" ::: "memory");
        slot = slotN;
    }

    // Epilogue: direct f32 stores (float2), every element covered.
#pragma unroll
    for (int mf = 0; mf < 4; mf++) {
#pragma unroll
        for (int nf = 0; nf < 8; nf++) {
            int m = m0 + wm * 64 + mf * 16 + (lane >> 2);
            int n = n0 + wn * 64 + nf * 8 + (lane & 3) * 2;
            float2* p0 = reinterpret_cast<float2*>(C + (size_t)m * OUT_F + n);
            *p0 = make_float2(acc[mf][nf][0], acc[mf][nf][1]);
            float2* p1 = reinterpret_cast<float2*>(C + (size_t)(m + 8) * OUT_F + n);
            *p1 = make_float2(acc[mf][nf][2], acc[mf][nf][3]);
        }
    }
}

// ---------------------------------------------------------------------------
extern "C" void kernel_launch(void* const* d_in, const int* in_sizes, int n_in,
                              void* d_out, int out_size) {
    (void)n_in; (void)out_size;
    float* out = (float*)d_out;   // [M, OUT_F] f32

    const int n_x = in_sizes[0];            // x element count (f32)
    const int M   = n_x / IN_F;             // 4096

    // 1) Fused prep: convert x -> fp16 g_X  +  dequant W -> fp16 g_W
    {
        int nconv = (n_x / 8 + 255) / 256;                  // convert blocks
        int ndeq  = (OUT_F * (IN_F / 8) + 255) / 256;       // dequant blocks
        prep_kernel<<<nconv + ndeq, 256>>>(
            (const float4*)d_in[0], n_x, nconv,
            (const int4*)d_in[1], (const float*)d_in[2], (const int*)d_in[3]);
    }

    // 2) Tensor-core GEMM (2 CTAs/SM)
    cudaFuncSetAttribute(gemm_kernel,
                         cudaFuncAttributeMaxDynamicSharedMemorySize,
                         STAGES * STAGE_BYTES);
    dim3 grid(M / BM, OUT_F / BN);   // (32, 86): M fastest -> N-band L2 reuse
    gemm_kernel<<<grid, 128, STAGES * STAGE_BYTES>>>(out);
}